// round 4
// baseline (speedup 1.0000x reference)
#include <cuda_runtime.h>
#include <cuda_bf16.h>

#define TOKENS 32768
#define DMODEL 4096
#define NEXP   64
#define BM     128
#define BK     32
#define NBLK_B (TOKENS / 256)   // 128 blocks in the gate kernel

// Scratch (no allocations allowed): h = tanh(x@w1^T), plus per-block partials.
__device__ float g_h[TOKENS * NEXP];
__device__ float g_imp[NBLK_B * NEXP];
__device__ int   g_load[NBLK_B * NEXP];

// ---- packed f32x2 helpers (FFMA2 — only reachable via PTX fma.rn.f32x2) ----
static __device__ __forceinline__ unsigned long long pack2(float lo, float hi) {
    unsigned long long r;
    asm("mov.b64 %0, {%1, %2};" : "=l"(r) : "f"(lo), "f"(hi));
    return r;
}
static __device__ __forceinline__ void unpack2(unsigned long long v, float& lo, float& hi) {
    asm("mov.b64 {%0, %1}, %2;" : "=f"(lo), "=f"(hi) : "l"(v));
}
static __device__ __forceinline__ void ffma2(unsigned long long& d,
                                             unsigned long long a,
                                             unsigned long long b) {
    asm("fma.rn.f32x2 %0, %1, %2, %0;" : "+l"(d) : "l"(a), "l"(b));
}

// ============================================================================
// Kernel A: h = tanh(x @ w1^T)   [32768,4096] x [64,4096]^T -> [32768,64]
// Block tile: 128 tokens x 64 experts, BK=32. 256 threads, each computes an
// 8-token x 4-expert microtile as 4 token-pairs x 4 experts in f32x2 regs.
// ============================================================================
__global__ void __launch_bounds__(256, 2)
gemm1_tanh(const float* __restrict__ x, const float* __restrict__ w1) {
    __shared__ float xs[BK][BM];     // xs[k][m] (transposed x tile)
    __shared__ float ws[BK][NEXP];   // ws[k][e]

    const int tid = threadIdx.x;
    const int bm  = blockIdx.x * BM;
    const int m0  = (tid & 15) * 8;   // token offset within tile (0..120)
    const int e0  = (tid >> 4) * 4;   // expert offset (0..60)

    unsigned long long acc[4][4];     // [token-pair][expert], bits 0 == (0.f,0.f)
#pragma unroll
    for (int p = 0; p < 4; p++)
#pragma unroll
        for (int e = 0; e < 4; e++) acc[p][e] = 0ull;

    for (int kk = 0; kk < DMODEL; kk += BK) {
        // load x tile: 128 rows x 32 k = 1024 float4, 4 per thread (coalesced)
#pragma unroll
        for (int i = 0; i < 4; i++) {
            int l = tid + 256 * i;
            int row = l >> 3, c4 = l & 7;
            float4 v = *reinterpret_cast<const float4*>(
                &x[(size_t)(bm + row) * DMODEL + kk + c4 * 4]);
            xs[c4 * 4 + 0][row] = v.x;
            xs[c4 * 4 + 1][row] = v.y;
            xs[c4 * 4 + 2][row] = v.z;
            xs[c4 * 4 + 3][row] = v.w;
        }
        // load w1 tile: 64 rows x 32 k = 512 float4, 2 per thread
#pragma unroll
        for (int i = 0; i < 2; i++) {
            int l = tid + 256 * i;
            int e = l >> 3, c4 = l & 7;
            float4 v = *reinterpret_cast<const float4*>(
                &w1[(size_t)e * DMODEL + kk + c4 * 4]);
            ws[c4 * 4 + 0][e] = v.x;
            ws[c4 * 4 + 1][e] = v.y;
            ws[c4 * 4 + 2][e] = v.z;
            ws[c4 * 4 + 3][e] = v.w;
        }
        __syncthreads();

#pragma unroll
        for (int k = 0; k < BK; k++) {
            // 8 consecutive tokens as 4 f32x2 pairs straight from shared
            const ulonglong2 xa = *reinterpret_cast<const ulonglong2*>(&xs[k][m0]);
            const ulonglong2 xb = *reinterpret_cast<const ulonglong2*>(&xs[k][m0 + 4]);
            unsigned long long xp[4] = {xa.x, xa.y, xb.x, xb.y};
            const float4 wv = *reinterpret_cast<const float4*>(&ws[k][e0]);
            unsigned long long wd[4] = {pack2(wv.x, wv.x), pack2(wv.y, wv.y),
                                        pack2(wv.z, wv.z), pack2(wv.w, wv.w)};
#pragma unroll
            for (int p = 0; p < 4; p++)
#pragma unroll
                for (int e = 0; e < 4; e++) ffma2(acc[p][e], xp[p], wd[e]);
        }
        __syncthreads();
    }

#pragma unroll
    for (int p = 0; p < 4; p++) {
        int tok = bm + m0 + 2 * p;
#pragma unroll
        for (int e = 0; e < 4; e++) {
            float lo, hi;
            unpack2(acc[p][e], lo, hi);
            g_h[(size_t)tok * NEXP + e0 + e]       = tanhf(lo);
            g_h[(size_t)(tok + 1) * NEXP + e0 + e] = tanhf(hi);
        }
    }
}

// ============================================================================
// Kernel B: logits = h @ w2^T; softmax; argmax(logits+noise); block partials.
// One thread per token, 256 tokens/block, w2 cached in shared.
// Importance sums are deterministic: warp butterfly -> per-warp slot -> fixed-
// order sum (no float atomics).
// ============================================================================
__global__ void __launch_bounds__(256)
gate_kernel(const float* __restrict__ w2, const float* __restrict__ noise,
            float* __restrict__ out) {
    __shared__ float w2s[NEXP][NEXP];
    __shared__ float s_imp[8][NEXP];
    __shared__ int   s_load[NEXP];

    const int tid  = threadIdx.x;
    const int warp = tid >> 5;

    for (int i = tid; i < NEXP * NEXP; i += 256) w2s[i >> 6][i & 63] = w2[i];
    if (tid < NEXP) s_load[tid] = 0;
    __syncthreads();

    const int t = blockIdx.x * 256 + tid;

    float l[NEXP];
#pragma unroll
    for (int e = 0; e < NEXP; e++) l[e] = 0.f;

    const float4* hrow = reinterpret_cast<const float4*>(&g_h[(size_t)t * NEXP]);
#pragma unroll 2
    for (int j4 = 0; j4 < 16; j4++) {
        float4 hv = hrow[j4];
#pragma unroll
        for (int e = 0; e < NEXP; e++) {
            l[e] += hv.x * w2s[e][4 * j4 + 0] + hv.y * w2s[e][4 * j4 + 1] +
                    hv.z * w2s[e][4 * j4 + 2] + hv.w * w2s[e][4 * j4 + 3];
        }
    }

    // softmax max
    float maxl = l[0];
#pragma unroll
    for (int e = 1; e < NEXP; e++) maxl = fmaxf(maxl, l[e]);

    // argmax of logits + gumbel noise (first occurrence on strict >)
    const float4* nrow = reinterpret_cast<const float4*>(&noise[(size_t)t * NEXP]);
    float best = -3.402823466e38f;
    int   bi   = 0;
#pragma unroll
    for (int e4 = 0; e4 < 16; e4++) {
        float4 nv = nrow[e4];
        float v;
        v = l[4 * e4 + 0] + nv.x; if (v > best) { best = v; bi = 4 * e4 + 0; }
        v = l[4 * e4 + 1] + nv.y; if (v > best) { best = v; bi = 4 * e4 + 1; }
        v = l[4 * e4 + 2] + nv.z; if (v > best) { best = v; bi = 4 * e4 + 2; }
        v = l[4 * e4 + 3] + nv.w; if (v > best) { best = v; bi = 4 * e4 + 3; }
    }

    // softmax denom
    float Z = 0.f;
#pragma unroll
    for (int e = 0; e < NEXP; e++) Z += expf(l[e] - maxl);
    const float inv = 1.0f / Z;

    // importance partials: butterfly per expert, lane0 writes per-warp slot
#pragma unroll
    for (int e = 0; e < NEXP; e++) {
        float v = expf(l[e] - maxl) * inv;
        v += __shfl_xor_sync(0xffffffffu, v, 16);
        v += __shfl_xor_sync(0xffffffffu, v, 8);
        v += __shfl_xor_sync(0xffffffffu, v, 4);
        v += __shfl_xor_sync(0xffffffffu, v, 2);
        v += __shfl_xor_sync(0xffffffffu, v, 1);
        if ((tid & 31) == 0) s_imp[warp][e] = v;
    }

    atomicAdd(&s_load[bi], 1);   // integer atomics: deterministic

    out[t]          = (float)bi;
    out[TOKENS + t] = best;

    __syncthreads();
    if (tid < NEXP) {
        float s = 0.f;
#pragma unroll
        for (int w = 0; w < 8; w++) s += s_imp[w][tid];
        g_imp[blockIdx.x * NEXP + tid]  = s;
        g_load[blockIdx.x * NEXP + tid] = s_load[tid];
    }
}

// ============================================================================
// Kernel C: reduce 128 block partials; write balance_loss, load_mean,
// importance_mean. Fixed-order sums -> deterministic.
// ============================================================================
__global__ void finalize_kernel(float* __restrict__ out) {
    __shared__ float red[NEXP];
    const int e = threadIdx.x;   // 64 threads

    float s  = 0.f;
    int   ld = 0;
    for (int b = 0; b < NBLK_B; b++) {
        s  += g_imp[b * NEXP + e];
        ld += g_load[b * NEXP + e];
    }
    const float imp_mean  = s * (1.0f / TOKENS);
    const float load_mean = (float)ld * (1.0f / TOKENS);

    out[2 * TOKENS + 1 + e]        = load_mean;
    out[2 * TOKENS + 1 + NEXP + e] = imp_mean;

    red[e] = imp_mean * load_mean;
    __syncthreads();
    if (e == 0) {
        float a = 0.f;
        for (int i = 0; i < NEXP; i++) a += red[i];
        out[2 * TOKENS] = (float)NEXP * a * 0.1f;
    }
}

extern "C" void kernel_launch(void* const* d_in, const int* in_sizes, int n_in,
                              void* d_out, int out_size) {
    const float* x     = (const float*)d_in[0];
    const float* w1    = (const float*)d_in[1];
    const float* w2    = (const float*)d_in[2];
    const float* noise = (const float*)d_in[3];
    float* out = (float*)d_out;

    gemm1_tanh<<<TOKENS / BM, 256>>>(x, w1);
    gate_kernel<<<NBLK_B, 256>>>(w2, noise, out);
    finalize_kernel<<<1, NEXP>>>(out);
}

// round 5
// speedup vs baseline: 1.9191x; 1.9191x over previous
#include <cuda_runtime.h>
#include <cuda_bf16.h>

#define TOKENS 32768
#define DMODEL 4096
#define NEXP   64
#define BM     128
#define BK     16
#define XPAD   140               // 128 + 12: 16B-aligned rows, low STS conflict
#define NBLK_B (TOKENS / 256)    // 128 blocks in the gate kernel

// Scratch (no allocations allowed): h = tanh(x@w1^T), plus per-block partials.
__device__ float g_h[TOKENS * NEXP];
__device__ float g_imp[NBLK_B * NEXP];
__device__ int   g_load[NBLK_B * NEXP];

// ---- packed f32x2 helpers (FFMA2 — only reachable via PTX fma.rn.f32x2) ----
static __device__ __forceinline__ unsigned long long pack2(float lo, float hi) {
    unsigned long long r;
    asm("mov.b64 %0, {%1, %2};" : "=l"(r) : "f"(lo), "f"(hi));
    return r;
}
static __device__ __forceinline__ void unpack2(unsigned long long v, float& lo, float& hi) {
    asm("mov.b64 {%0, %1}, %2;" : "=f"(lo), "=f"(hi) : "l"(v));
}
static __device__ __forceinline__ void ffma2(unsigned long long& d,
                                             unsigned long long a,
                                             unsigned long long b) {
    asm("fma.rn.f32x2 %0, %1, %2, %0;" : "+l"(d) : "l"(a), "l"(b));
}

// ============================================================================
// Kernel A: h = tanh(x @ w1^T)   [32768,4096] x [64,4096]^T -> [32768,64]
//
// Block: 128 tokens x 64 experts, 256 threads (8 warps).
//   warp w  -> experts 8w..8w+7 (w-values warp-uniform -> broadcast LDS)
//   lane L  -> tokens  4L..4L+3 (one conflict-free LDS.128 per k)
// Per thread: 4 tokens x 8 experts = 16 f32x2 accumulators.
// BK=16 k-slab, register-staged double buffering (prefetch LDG during compute).
// ============================================================================
__global__ void __launch_bounds__(256, 2)
gemm1_tanh(const float* __restrict__ x, const float* __restrict__ w1) {
    __shared__ __align__(16) float xs[BK][XPAD];   // xs[k][token]
    __shared__ __align__(16) float ws[BK][NEXP];   // ws[k][expert]

    const int tid  = threadIdx.x;
    const int lane = tid & 31;
    const int warp = tid >> 5;
    const int bm   = blockIdx.x * BM;
    const int e0   = warp * 8;

    // loader mapping: each thread moves 2 float4 of x and 1 float4 of w per tile
    const int row0 = tid >> 2;        // 0..63
    const int row1 = row0 + 64;       // 64..127
    const int c4   = tid & 3;         // k-chunk within BK (4 floats)

    unsigned long long acc[2][8];     // [token-pair][expert]
#pragma unroll
    for (int p = 0; p < 2; p++)
#pragma unroll
        for (int e = 0; e < 8; e++) acc[p][e] = 0ull;

    // ---- prologue: load tile 0 ----
    float4 xr0 = *reinterpret_cast<const float4*>(&x[(size_t)(bm + row0) * DMODEL + c4 * 4]);
    float4 xr1 = *reinterpret_cast<const float4*>(&x[(size_t)(bm + row1) * DMODEL + c4 * 4]);
    float4 wr  = *reinterpret_cast<const float4*>(&w1[(size_t)row0 * DMODEL + c4 * 4]);

    xs[c4 * 4 + 0][row0] = xr0.x;  xs[c4 * 4 + 1][row0] = xr0.y;
    xs[c4 * 4 + 2][row0] = xr0.z;  xs[c4 * 4 + 3][row0] = xr0.w;
    xs[c4 * 4 + 0][row1] = xr1.x;  xs[c4 * 4 + 1][row1] = xr1.y;
    xs[c4 * 4 + 2][row1] = xr1.z;  xs[c4 * 4 + 3][row1] = xr1.w;
    ws[c4 * 4 + 0][row0] = wr.x;   ws[c4 * 4 + 1][row0] = wr.y;
    ws[c4 * 4 + 2][row0] = wr.z;   ws[c4 * 4 + 3][row0] = wr.w;
    __syncthreads();

    const int NT = DMODEL / BK;   // 256 k-slabs
    for (int kt = 0; kt < NT; kt++) {
        // prefetch next slab into registers (overlaps with compute below)
        if (kt + 1 < NT) {
            const int kk = (kt + 1) * BK;
            xr0 = *reinterpret_cast<const float4*>(&x[(size_t)(bm + row0) * DMODEL + kk + c4 * 4]);
            xr1 = *reinterpret_cast<const float4*>(&x[(size_t)(bm + row1) * DMODEL + kk + c4 * 4]);
            wr  = *reinterpret_cast<const float4*>(&w1[(size_t)row0 * DMODEL + kk + c4 * 4]);
        }

#pragma unroll
        for (int k = 0; k < BK; k++) {
            // 4 tokens = 2 f32x2 pairs, one conflict-free LDS.128
            const ulonglong2 xa = *reinterpret_cast<const ulonglong2*>(&xs[k][lane * 4]);
            // 8 warp-uniform w values (broadcast LDS), duplicated in regs
            const float4 wa = *reinterpret_cast<const float4*>(&ws[k][e0]);
            const float4 wb = *reinterpret_cast<const float4*>(&ws[k][e0 + 4]);
            unsigned long long wd[8];
            wd[0] = pack2(wa.x, wa.x); wd[1] = pack2(wa.y, wa.y);
            wd[2] = pack2(wa.z, wa.z); wd[3] = pack2(wa.w, wa.w);
            wd[4] = pack2(wb.x, wb.x); wd[5] = pack2(wb.y, wb.y);
            wd[6] = pack2(wb.z, wb.z); wd[7] = pack2(wb.w, wb.w);
#pragma unroll
            for (int e = 0; e < 8; e++) {
                ffma2(acc[0][e], xa.x, wd[e]);
                ffma2(acc[1][e], xa.y, wd[e]);
            }
        }

        if (kt + 1 < NT) {
            __syncthreads();   // everyone done reading this slab
            xs[c4 * 4 + 0][row0] = xr0.x;  xs[c4 * 4 + 1][row0] = xr0.y;
            xs[c4 * 4 + 2][row0] = xr0.z;  xs[c4 * 4 + 3][row0] = xr0.w;
            xs[c4 * 4 + 0][row1] = xr1.x;  xs[c4 * 4 + 1][row1] = xr1.y;
            xs[c4 * 4 + 2][row1] = xr1.z;  xs[c4 * 4 + 3][row1] = xr1.w;
            ws[c4 * 4 + 0][row0] = wr.x;   ws[c4 * 4 + 1][row0] = wr.y;
            ws[c4 * 4 + 2][row0] = wr.z;   ws[c4 * 4 + 3][row0] = wr.w;
            __syncthreads();   // slab visible
        }
    }

    // ---- epilogue: tanh + store 4 tokens x 8 experts ----
#pragma unroll
    for (int p = 0; p < 2; p++) {
        float lo[8], hi[8];
#pragma unroll
        for (int e = 0; e < 8; e++) unpack2(acc[p][e], lo[e], hi[e]);
        const int t0 = bm + lane * 4 + 2 * p;
        float* d0 = &g_h[(size_t)t0 * NEXP + e0];
        float* d1 = d0 + NEXP;
        *reinterpret_cast<float4*>(d0) =
            make_float4(tanhf(lo[0]), tanhf(lo[1]), tanhf(lo[2]), tanhf(lo[3]));
        *reinterpret_cast<float4*>(d0 + 4) =
            make_float4(tanhf(lo[4]), tanhf(lo[5]), tanhf(lo[6]), tanhf(lo[7]));
        *reinterpret_cast<float4*>(d1) =
            make_float4(tanhf(hi[0]), tanhf(hi[1]), tanhf(hi[2]), tanhf(hi[3]));
        *reinterpret_cast<float4*>(d1 + 4) =
            make_float4(tanhf(hi[4]), tanhf(hi[5]), tanhf(hi[6]), tanhf(hi[7]));
    }
}

// ============================================================================
// Kernel B: logits = h @ w2^T; softmax; argmax(logits+noise); block partials.
// One thread per token, 256 tokens/block, w2 cached in shared.
// Importance sums are deterministic: warp butterfly -> per-warp slot -> fixed-
// order sum (no float atomics).
// ============================================================================
__global__ void __launch_bounds__(256)
gate_kernel(const float* __restrict__ w2, const float* __restrict__ noise,
            float* __restrict__ out) {
    __shared__ float w2s[NEXP][NEXP];
    __shared__ float s_imp[8][NEXP];
    __shared__ int   s_load[NEXP];

    const int tid  = threadIdx.x;
    const int warp = tid >> 5;

    for (int i = tid; i < NEXP * NEXP; i += 256) w2s[i >> 6][i & 63] = w2[i];
    if (tid < NEXP) s_load[tid] = 0;
    __syncthreads();

    const int t = blockIdx.x * 256 + tid;

    float l[NEXP];
#pragma unroll
    for (int e = 0; e < NEXP; e++) l[e] = 0.f;

    const float4* hrow = reinterpret_cast<const float4*>(&g_h[(size_t)t * NEXP]);
#pragma unroll 2
    for (int j4 = 0; j4 < 16; j4++) {
        float4 hv = hrow[j4];
#pragma unroll
        for (int e = 0; e < NEXP; e++) {
            l[e] += hv.x * w2s[e][4 * j4 + 0] + hv.y * w2s[e][4 * j4 + 1] +
                    hv.z * w2s[e][4 * j4 + 2] + hv.w * w2s[e][4 * j4 + 3];
        }
    }

    // softmax max
    float maxl = l[0];
#pragma unroll
    for (int e = 1; e < NEXP; e++) maxl = fmaxf(maxl, l[e]);

    // argmax of logits + gumbel noise (first occurrence on strict >)
    const float4* nrow = reinterpret_cast<const float4*>(&noise[(size_t)t * NEXP]);
    float best = -3.402823466e38f;
    int   bi   = 0;
#pragma unroll
    for (int e4 = 0; e4 < 16; e4++) {
        float4 nv = nrow[e4];
        float v;
        v = l[4 * e4 + 0] + nv.x; if (v > best) { best = v; bi = 4 * e4 + 0; }
        v = l[4 * e4 + 1] + nv.y; if (v > best) { best = v; bi = 4 * e4 + 1; }
        v = l[4 * e4 + 2] + nv.z; if (v > best) { best = v; bi = 4 * e4 + 2; }
        v = l[4 * e4 + 3] + nv.w; if (v > best) { best = v; bi = 4 * e4 + 3; }
    }

    // softmax denom
    float Z = 0.f;
#pragma unroll
    for (int e = 0; e < NEXP; e++) Z += expf(l[e] - maxl);
    const float inv = 1.0f / Z;

    // importance partials: butterfly per expert, lane0 writes per-warp slot
#pragma unroll
    for (int e = 0; e < NEXP; e++) {
        float v = expf(l[e] - maxl) * inv;
        v += __shfl_xor_sync(0xffffffffu, v, 16);
        v += __shfl_xor_sync(0xffffffffu, v, 8);
        v += __shfl_xor_sync(0xffffffffu, v, 4);
        v += __shfl_xor_sync(0xffffffffu, v, 2);
        v += __shfl_xor_sync(0xffffffffu, v, 1);
        if ((tid & 31) == 0) s_imp[warp][e] = v;
    }

    atomicAdd(&s_load[bi], 1);   // integer atomics: deterministic

    out[t]          = (float)bi;
    out[TOKENS + t] = best;

    __syncthreads();
    if (tid < NEXP) {
        float s = 0.f;
#pragma unroll
        for (int w = 0; w < 8; w++) s += s_imp[w][tid];
        g_imp[blockIdx.x * NEXP + tid]  = s;
        g_load[blockIdx.x * NEXP + tid] = s_load[tid];
    }
}

// ============================================================================
// Kernel C: reduce 128 block partials; write balance_loss, load_mean,
// importance_mean. Fixed-order sums -> deterministic.
// ============================================================================
__global__ void finalize_kernel(float* __restrict__ out) {
    __shared__ float red[NEXP];
    const int e = threadIdx.x;   // 64 threads

    float s  = 0.f;
    int   ld = 0;
    for (int b = 0; b < NBLK_B; b++) {
        s  += g_imp[b * NEXP + e];
        ld += g_load[b * NEXP + e];
    }
    const float imp_mean  = s * (1.0f / TOKENS);
    const float load_mean = (float)ld * (1.0f / TOKENS);

    out[2 * TOKENS + 1 + e]        = load_mean;
    out[2 * TOKENS + 1 + NEXP + e] = imp_mean;

    red[e] = imp_mean * load_mean;
    __syncthreads();
    if (e == 0) {
        float a = 0.f;
        for (int i = 0; i < NEXP; i++) a += red[i];
        out[2 * TOKENS] = (float)NEXP * a * 0.1f;
    }
}

extern "C" void kernel_launch(void* const* d_in, const int* in_sizes, int n_in,
                              void* d_out, int out_size) {
    const float* x     = (const float*)d_in[0];
    const float* w1    = (const float*)d_in[1];
    const float* w2    = (const float*)d_in[2];
    const float* noise = (const float*)d_in[3];
    float* out = (float*)d_out;

    gemm1_tanh<<<TOKENS / BM, 256>>>(x, w1);
    gate_kernel<<<NBLK_B, 256>>>(w2, noise, out);
    finalize_kernel<<<1, NEXP>>>(out);
}